// round 4
// baseline (speedup 1.0000x reference)
#include <cuda_runtime.h>

#define HDIM  1024
#define BATCH 256
#define TLEN  512
#define NCTA  128
#define BM    64
#define BN    32
#define BK    32
#define AST   65   // As stride in float2 units (padding for conflict-free smem)

// ---- smem layout (floats): Wsm[32768] | As2(u64)[2*32*65] | xs[64] | red[256] | wout[1024]
#define SMEM_FLOATS (32768 + 2*BK*AST*2 + 64 + 256 + 1024)
#define SMEM_BYTES  (SMEM_FLOATS * 4)

// -------- device scratch --------
__device__ float g_hA[BATCH * HDIM];
__device__ float g_hB[BATCH * HDIM];
__device__ float g_out[BATCH * TLEN];
__device__ float g_feat[BATCH * 3];
__device__ float g_lossnum;
__device__ unsigned g_count;            // monotonic across replays
__device__ volatile unsigned g_release; // monotonic across replays

// -------- f32x2 helpers --------
__device__ __forceinline__ unsigned long long pack2(float lo, float hi) {
    unsigned long long r;
    asm("mov.b64 %0, {%1, %2};" : "=l"(r) : "f"(lo), "f"(hi));
    return r;
}
__device__ __forceinline__ void unpack2(unsigned long long v, float& lo, float& hi) {
    asm("mov.b64 {%0, %1}, %2;" : "=f"(lo), "=f"(hi) : "l"(v));
}
__device__ __forceinline__ void fma2(unsigned long long& acc,
                                     unsigned long long a, unsigned long long b) {
    asm("fma.rn.f32x2 %0, %1, %2, %0;" : "+l"(acc) : "l"(a), "l"(b));
}

// -------- grid barrier: epoch-based, monotonic, replay-safe --------
__device__ __forceinline__ void gsync(unsigned& epoch) {
    __syncthreads();
    if (threadIdx.x == 0) {
        epoch++;
        __threadfence();
        unsigned old = atomicAdd(&g_count, 1u);
        if (old == epoch * NCTA - 1u) {
            __threadfence();
            g_release = epoch;
        } else {
            while (g_release < epoch) { __nanosleep(32); }
            __threadfence();
        }
    }
    __syncthreads();
}

extern "C" __global__ void __launch_bounds__(256, 1) persist_kernel(
    const float* __restrict__ input, const int* __restrict__ seqlen,
    const float* __restrict__ Wih_e, const float* __restrict__ Whh_e,
    const float* __restrict__ bih_e, const float* __restrict__ bhh_e,
    const float* __restrict__ Wenc,  const float* __restrict__ benc,
    const float* __restrict__ Wdec,  const float* __restrict__ bdec,
    const float* __restrict__ Wih_d, const float* __restrict__ Whh_d,
    const float* __restrict__ bih_d, const float* __restrict__ bhh_d,
    const float* __restrict__ Wout,  const float* __restrict__ bout,
    float* __restrict__ dout, int out_size)
{
    extern __shared__ float smem[];
    float* Wsm = smem;                                                  // 1024 x 32
    unsigned long long* As2 = (unsigned long long*)(smem + 32768);      // 2 x 32 x 65
    float* xs      = smem + 32768 + 2 * BK * AST * 2;                   // 64
    float* red     = xs + 64;                                           // 256
    float* wout_sh = red + 256;                                         // 1024

    const int tid = threadIdx.x;
    const int bx  = blockIdx.x;
    const int nt  = bx & 31;        // 32 n-tiles
    const int mt  = bx >> 5;        // 4  m-tiles
    const int nblk = nt * BN;
    const int m0   = mt * BM;
    const int m_local = (tid & 15) | (((tid >> 6) & 3) << 4);  // 0..63
    const int ng      = (tid >> 4) & 3;                        // 0..3
    const float bout0 = bout[0];

    unsigned epoch = g_release;   // stable base from previous replay

    // ---- init: zero h0 (encoder), reset loss ----
    {
        int gtid = bx * 256 + tid;
#pragma unroll
        for (int r = 0; r < 8; r++) g_hA[gtid + r * 32768] = 0.f;
        if (gtid == 0) g_lossnum = 0.f;
    }
    gsync(epoch);

    // ================= two RNN phases =================
    for (int phase = 0; phase < 2; phase++) {
        const float* Whh = phase ? Whh_d : Whh_e;
        const float* Wih = phase ? Wih_d : Wih_e;
        const float* bih = phase ? bih_d : bih_e;
        const float* bhh = phase ? bhh_d : bhh_e;

        // preload this CTA's Whh slice (BN rows x HDIM) into smem, transposed [k][nn]
        for (int i = tid; i < BN * HDIM / 4; i += 256) {
            int nn = i >> 8;       // 0..31
            int kq = i & 255;      // float4 index along k
            float4 v = *(const float4*)(Whh + (nblk + nn) * HDIM + kq * 4);
            Wsm[(kq * 4 + 0) * BN + nn] = v.x;
            Wsm[(kq * 4 + 1) * BN + nn] = v.y;
            Wsm[(kq * 4 + 2) * BN + nn] = v.z;
            Wsm[(kq * 4 + 3) * BN + nn] = v.w;
        }
        if (phase == 1)
            for (int i = tid; i < HDIM; i += 256) wout_sh[i] = Wout[i];

        // per-thread constants for this phase
        const int n0 = nblk + ng * 8;
        unsigned long long wih2[4], bias2[4];
#pragma unroll
        for (int j = 0; j < 4; j++) {
            wih2[j]  = pack2(Wih[n0 + 2 * j], Wih[n0 + 2 * j + 1]);
            bias2[j] = pack2(bih[n0 + 2 * j] + bhh[n0 + 2 * j],
                             bih[n0 + 2 * j + 1] + bhh[n0 + 2 * j + 1]);
        }
        __syncthreads();

        float* h_old = g_hA;
        float* h_new = g_hB;

        for (int t = 0; t < TLEN; t++) {
            // ---- per-row scalar input x ----
            if (phase == 0) {
                if (tid < BM) xs[tid] = input[(m0 + tid) * TLEN + t];
            } else {
                // redundant per-CTA dot(h_old[row,:], Wout)
                int row = tid >> 2, seg = tid & 3;
                const float* hp = h_old + (m0 + row) * HDIM + seg * 256;
                const float* wp = wout_sh + seg * 256;
                float s = 0.f;
#pragma unroll 8
                for (int k = 0; k < 256; k += 4) {
                    float4 hv = *(const float4*)(hp + k);
                    float4 wv = *(const float4*)(wp + k);
                    s = fmaf(hv.x, wv.x, s); s = fmaf(hv.y, wv.y, s);
                    s = fmaf(hv.z, wv.z, s); s = fmaf(hv.w, wv.w, s);
                }
                red[tid] = s;
                __syncthreads();
                if (tid < BM) {
                    float v = red[tid * 4] + red[tid * 4 + 1] +
                              red[tid * 4 + 2] + red[tid * 4 + 3] + bout0;
                    if (t > 0) {
                        xs[tid] = v;
                        if (nt == 0) g_out[(m0 + tid) * TLEN + (t - 1)] = v;
                    } else xs[tid] = 0.f;
                }
            }
            __syncthreads();

            float x = xs[m_local];
            unsigned long long x2 = pack2(x, x);
            unsigned long long acc2[4];
#pragma unroll
            for (int j = 0; j < 4; j++) { acc2[j] = bias2[j]; fma2(acc2[j], x2, wih2[j]); }

            // ---- stream A (h_old rows) through double-buffered smem ----
            float4 areg[2];
#pragma unroll
            for (int r = 0; r < 2; r++) {
                int idx = tid + r * 256, mm = idx >> 3, kq = idx & 7;
                areg[r] = *(const float4*)(h_old + (m0 + mm) * HDIM + kq * 4);
            }
            int buf = 0;
            for (int k0 = 0; k0 < HDIM; k0 += BK) {
                unsigned long long* Ab = As2 + buf * BK * AST;
#pragma unroll
                for (int r = 0; r < 2; r++) {
                    int idx = tid + r * 256, mm = idx >> 3, kq = idx & 7;
                    Ab[(kq * 4 + 0) * AST + mm] = pack2(areg[r].x, areg[r].x);
                    Ab[(kq * 4 + 1) * AST + mm] = pack2(areg[r].y, areg[r].y);
                    Ab[(kq * 4 + 2) * AST + mm] = pack2(areg[r].z, areg[r].z);
                    Ab[(kq * 4 + 3) * AST + mm] = pack2(areg[r].w, areg[r].w);
                }
                __syncthreads();
                if (k0 + BK < HDIM) {
#pragma unroll
                    for (int r = 0; r < 2; r++) {
                        int idx = tid + r * 256, mm = idx >> 3, kq = idx & 7;
                        areg[r] = *(const float4*)(h_old + (m0 + mm) * HDIM + k0 + BK + kq * 4);
                    }
                }
                const float* wp = Wsm + k0 * BN + ng * 8;
#pragma unroll 8
                for (int kk = 0; kk < BK; kk++) {
                    unsigned long long a2 = Ab[kk * AST + m_local];
                    ulonglong2 wa = *(const ulonglong2*)(wp + kk * BN);
                    ulonglong2 wb = *(const ulonglong2*)(wp + kk * BN + 4);
                    fma2(acc2[0], a2, wa.x); fma2(acc2[1], a2, wa.y);
                    fma2(acc2[2], a2, wb.x); fma2(acc2[3], a2, wb.y);
                }
                buf ^= 1;
            }

            // ---- tanh + store ----
            float o[8];
#pragma unroll
            for (int j = 0; j < 4; j++) unpack2(acc2[j], o[2 * j], o[2 * j + 1]);
            float4 r0 = make_float4(tanhf(o[0]), tanhf(o[1]), tanhf(o[2]), tanhf(o[3]));
            float4 r1 = make_float4(tanhf(o[4]), tanhf(o[5]), tanhf(o[6]), tanhf(o[7]));
            float* hw = h_new + (m0 + m_local) * HDIM + n0;
            *(float4*)(hw) = r0;
            *(float4*)(hw + 4) = r1;

            gsync(epoch);
            float* tmp = h_old; h_old = h_new; h_new = tmp;
        } // t  (final h is in g_hA: 512 swaps)

        if (phase == 0) {
            // ---- features = sigmoid(hT @ Wenc^T + benc) ----
            int wid = tid >> 5, lane = tid & 31;
            if (wid < 6) {
                int d = bx * 6 + wid;              // 0..767
                int b = d / 3, e = d - b * 3;
                const float* hp = g_hA + b * HDIM;
                const float* wp = Wenc + e * HDIM;
                float s = 0.f;
                for (int k = lane * 4; k < HDIM; k += 128) {
                    float4 hv = *(const float4*)(hp + k);
                    float4 wv = *(const float4*)(wp + k);
                    s = fmaf(hv.x, wv.x, s); s = fmaf(hv.y, wv.y, s);
                    s = fmaf(hv.z, wv.z, s); s = fmaf(hv.w, wv.w, s);
                }
#pragma unroll
                for (int o = 16; o; o >>= 1) s += __shfl_xor_sync(0xffffffff, s, o);
                if (lane == 0) g_feat[b * 3 + e] = 1.f / (1.f + expf(-(s + benc[e])));
            }
            gsync(epoch);
            // ---- h0 = features @ Wdec^T + bdec into g_hA ----
#pragma unroll
            for (int r = 0; r < 8; r++) {
                int i = bx * 2048 + r * 256 + tid;
                int b = i >> 10, j = i & 1023;
                g_hA[i] = bdec[j] + g_feat[b * 3] * Wdec[j * 3]
                                  + g_feat[b * 3 + 1] * Wdec[j * 3 + 1]
                                  + g_feat[b * 3 + 2] * Wdec[j * 3 + 2];
            }
            gsync(epoch);
        }
    } // phases

    // ---- tail: out[:, T-1] = dot(h_T, Wout) + bout (2 rows per CTA) ----
    {
        int half = tid >> 7, l = tid & 127;
        int b = bx * 2 + half;
        const float* hp = g_hA + b * HDIM;
        float s = 0.f;
        for (int k = l * 4; k < HDIM; k += 512) {
            float4 hv = *(const float4*)(hp + k);
            float4 wv = *(const float4*)(Wout + k);
            s = fmaf(hv.x, wv.x, s); s = fmaf(hv.y, wv.y, s);
            s = fmaf(hv.z, wv.z, s); s = fmaf(hv.w, wv.w, s);
        }
#pragma unroll
        for (int o = 16; o; o >>= 1) s += __shfl_xor_sync(0xffffffff, s, o);
        if ((tid & 31) == 0) red[tid >> 5] = s;
        __syncthreads();
        if (tid == 0) {
            g_out[(bx * 2) * TLEN + TLEN - 1]     = red[0] + red[1] + red[2] + red[3] + bout0;
            g_out[(bx * 2 + 1) * TLEN + TLEN - 1] = red[4] + red[5] + red[6] + red[7] + bout0;
        }
        __syncthreads();
    }

    // ---- masked MSE numerator (2 rows per CTA, same rows as tail) ----
    {
        int half = tid >> 7, l = tid & 127;
        int b = bx * 2 + half;
        int L = seqlen[b];
        float s = 0.f;
        for (int t = l; t < L; t += 128) {
            float d = input[b * TLEN + t] - g_out[b * TLEN + t];
            s = fmaf(d, d, s);
        }
#pragma unroll
        for (int o = 16; o; o >>= 1) s += __shfl_xor_sync(0xffffffff, s, o);
        if ((tid & 31) == 0) red[tid >> 5] = s;
        __syncthreads();
        if (tid == 0)
            atomicAdd(&g_lossnum, red[0] + red[1] + red[2] + red[3] +
                                  red[4] + red[5] + red[6] + red[7]);
        __syncthreads();
    }
    gsync(epoch);

    // ---- finalize loss (CTA 0) ----
    if (bx == 0) {
        red[tid] = (float)seqlen[tid];   // BATCH == 256 == blockDim
        __syncthreads();
        for (int o = 128; o; o >>= 1) {
            if (tid < o) red[tid] += red[tid + o];
            __syncthreads();
        }
        if (tid == 0 && out_size > 0) dout[0] = g_lossnum / red[0];
    }

    // ---- pack (loss, input, output, features) into dout ----
    {
        int chunk = (out_size + NCTA - 1) / NCTA;
        int lo = bx * chunk;
        int hi = lo + chunk; if (hi > out_size) hi = out_size;
        for (int i = lo + tid; i < hi; i += 256) {
            if (i == 0) continue;
            int j = i - 1;
            if (j < BATCH * TLEN) { dout[i] = input[j]; continue; }
            j -= BATCH * TLEN;
            if (j < BATCH * TLEN) { dout[i] = g_out[j]; continue; }
            j -= BATCH * TLEN;
            if (j < BATCH * 3) { dout[i] = g_feat[j]; continue; }
            dout[i] = 0.f;
        }
    }
}

extern "C" void kernel_launch(void* const* d_in, const int* in_sizes, int n_in,
                              void* d_out, int out_size) {
    const float* input  = (const float*)d_in[0];
    const int*   seqlen = (const int*)d_in[1];
    const float* Wih_e = (const float*)d_in[2];
    const float* Whh_e = (const float*)d_in[3];
    const float* bih_e = (const float*)d_in[4];
    const float* bhh_e = (const float*)d_in[5];
    const float* Wenc  = (const float*)d_in[6];
    const float* benc  = (const float*)d_in[7];
    const float* Wdec  = (const float*)d_in[8];
    const float* bdec  = (const float*)d_in[9];
    const float* Wih_d = (const float*)d_in[10];
    const float* Whh_d = (const float*)d_in[11];
    const float* bih_d = (const float*)d_in[12];
    const float* bhh_d = (const float*)d_in[13];
    const float* Wout  = (const float*)d_in[14];
    const float* bout  = (const float*)d_in[15];

    cudaFuncSetAttribute(persist_kernel,
                         cudaFuncAttributeMaxDynamicSharedMemorySize, SMEM_BYTES);
    persist_kernel<<<NCTA, 256, SMEM_BYTES>>>(
        input, seqlen, Wih_e, Whh_e, bih_e, bhh_e, Wenc, benc,
        Wdec, bdec, Wih_d, Whh_d, bih_d, bhh_d, Wout, bout,
        (float*)d_out, out_size);
}

// round 6
// speedup vs baseline: 3.6241x; 3.6241x over previous
#include <cuda_runtime.h>
#include <cuda_bf16.h>
#include <cstdint>

#define HDIM  1024
#define BATCH 256
#define TLEN  512
#define NCTA  128

// ---- dynamic smem layout (bytes) ----
// W2: 32 rows x RSB, each row = 512 k-pairs of uint2 {hi(k),hi(k+1) | lo(k),lo(k+1)}
#define RSB    4128            // 4096 + 32 pad -> conflict-free LDS.64
#define O_W2   0               // 132096 bytes
#define O_P    132096          // float[4][64][36] = 36864
#define O_XS   168960          // float[64]
#define O_BIAS 169216          // float[32]
#define O_WIH  169344          // float[32]
#define O_WOUT 169472          // float[32]
#define O_RED  169600          // float[256]
#define SMEM_BYTES 170624

// -------- device scratch --------
__device__ __align__(16) uint32_t g_hpk[2][BATCH * HDIM];  // packed: lo16=hi-bf16, hi16=lo-bf16
__device__ float g_xpart[2][32][BATCH];
__device__ float g_out[BATCH * TLEN];
__device__ float g_feat[BATCH * 3];
__device__ float g_lossnum;
__device__ unsigned g_count;
__device__ volatile unsigned g_release;

// -------- helpers --------
__device__ __forceinline__ uint32_t prmt(uint32_t a, uint32_t b, uint32_t s) {
    uint32_t d;
    asm("prmt.b32 %0, %1, %2, %3;" : "=r"(d) : "r"(a), "r"(b), "r"(s));
    return d;
}
__device__ __forceinline__ void mma_bf16(float c[4], uint32_t a0, uint32_t a1,
                                         uint32_t a2, uint32_t a3,
                                         uint32_t b0, uint32_t b1) {
    asm volatile(
        "mma.sync.aligned.m16n8k16.row.col.f32.bf16.bf16.f32 "
        "{%0,%1,%2,%3}, {%4,%5,%6,%7}, {%8,%9}, {%0,%1,%2,%3};"
        : "+f"(c[0]), "+f"(c[1]), "+f"(c[2]), "+f"(c[3])
        : "r"(a0), "r"(a1), "r"(a2), "r"(a3), "r"(b0), "r"(b1));
}
__device__ __forceinline__ uint32_t packsplit(float v) {
    __nv_bfloat16 hi = __float2bfloat16(v);
    __nv_bfloat16 lo = __float2bfloat16(v - __bfloat162float(hi));
    return (uint32_t)__bfloat16_as_ushort(hi) | ((uint32_t)__bfloat16_as_ushort(lo) << 16);
}
__device__ __forceinline__ float unpacksum(uint32_t w) {
    return __bfloat162float(__ushort_as_bfloat16((unsigned short)(w & 0xffffu))) +
           __bfloat162float(__ushort_as_bfloat16((unsigned short)(w >> 16)));
}

// -------- grid barrier (monotonic, replay-safe) --------
__device__ __forceinline__ void gsync(unsigned& epoch) {
    __syncthreads();
    if (threadIdx.x == 0) {
        epoch++;
        __threadfence();
        unsigned old = atomicAdd(&g_count, 1u);
        if (old == epoch * NCTA - 1u) {
            __threadfence();
            g_release = epoch;
        } else {
            while (g_release < epoch) { __nanosleep(32); }
            __threadfence();
        }
    }
    __syncthreads();
}

extern "C" __global__ void __launch_bounds__(256, 1) persist_mma(
    const float* __restrict__ input, const int* __restrict__ seqlen,
    const float* __restrict__ Wih_e, const float* __restrict__ Whh_e,
    const float* __restrict__ bih_e, const float* __restrict__ bhh_e,
    const float* __restrict__ Wenc,  const float* __restrict__ benc,
    const float* __restrict__ Wdec,  const float* __restrict__ bdec,
    const float* __restrict__ Wih_d, const float* __restrict__ Whh_d,
    const float* __restrict__ bih_d, const float* __restrict__ bhh_d,
    const float* __restrict__ Wout,  const float* __restrict__ bout,
    float* __restrict__ dout, int out_size)
{
    extern __shared__ __align__(16) char sc[];
    float* Psm     = (float*)(sc + O_P);
    float* xs      = (float*)(sc + O_XS);
    float* bias_sh = (float*)(sc + O_BIAS);
    float* wih_sh  = (float*)(sc + O_WIH);
    float* wout_sh = (float*)(sc + O_WOUT);
    float* red_f   = (float*)(sc + O_RED);

    const int tid  = threadIdx.x;
    const int wid  = tid >> 5;
    const int lane = tid & 31;
    const int g    = lane >> 2;     // group 0..7
    const int tg   = lane & 3;      // thread-in-group
    const int wm   = wid & 1;       // m-half (m32)
    const int kw   = wid >> 1;      // k-split 0..3
    const int bx   = blockIdx.x;
    const int nt   = bx & 31;
    const int mt   = bx >> 5;
    const int n0   = nt * 32;
    const int m0   = mt * 64;
    const float bout0 = bout[0];

    unsigned epoch = g_release;

    // ---- init: zero h buf 0, loss ----
    {
        int gtid = bx * 256 + tid;                 // 32768 threads
        uint4 z = make_uint4(0, 0, 0, 0);
        *(uint4*)(g_hpk[0] + gtid * 8)     = z;    // 262144 words total
        *(uint4*)(g_hpk[0] + gtid * 8 + 4) = z;
        if (gtid == 0) g_lossnum = 0.f;
    }
    gsync(epoch);

    // ================= two RNN phases =================
    for (int phase = 0; phase < 2; phase++) {
        const float* Whh = phase ? Whh_d : Whh_e;
        const float* Wih = phase ? Wih_d : Wih_e;
        const float* bih = phase ? bih_d : bih_e;
        const float* bhh = phase ? bhh_d : bhh_e;

        // ---- preload W slice: 32 rows x 1024, bf16 hi/lo interleaved per k-pair ----
        for (int i = tid; i < 32 * HDIM; i += 256) {
            int nn = i >> 10, k = i & 1023;
            float w = Whh[(size_t)(n0 + nn) * HDIM + k];
            __nv_bfloat16 hi = __float2bfloat16(w);
            __nv_bfloat16 lo = __float2bfloat16(w - __bfloat162float(hi));
            char* base = sc + O_W2 + nn * RSB + (k >> 1) * 8 + (k & 1) * 2;
            *(__nv_bfloat16*)base       = hi;
            *(__nv_bfloat16*)(base + 4) = lo;
        }
        if (tid < 32) {
            bias_sh[tid] = bih[n0 + tid] + bhh[n0 + tid];
            wih_sh[tid]  = Wih[n0 + tid];
            wout_sh[tid] = Wout[n0 + tid];
        }
        __syncthreads();

        for (int t = 0; t < TLEN; t++) {
            const int rp = t & 1;
            const uint2* hp = (const uint2*)g_hpk[rp];

            // ---- assemble per-row scalar x into xs ----
            if (tid < 64) {
                float xv = 0.f;
                int row = m0 + tid;
                if (phase == 0) {
                    xv = input[(size_t)row * TLEN + t];
                } else if (t > 0) {
                    float s = 0.f;
                    const float* xp = &g_xpart[(t - 1) & 1][0][row];
#pragma unroll
                    for (int j = 0; j < 32; j++) s += __ldcg(xp + j * BATCH);
                    xv = s + bout0;
                    if (nt == 0) g_out[(size_t)row * TLEN + (t - 1)] = xv;
                }
                xs[tid] = xv;
            }

            // ---- MMA mainloop: warp tile m32 x n32 over K=256 (k-split) ----
            float acc[2][4][4];
#pragma unroll
            for (int mi = 0; mi < 2; mi++)
#pragma unroll
                for (int nb = 0; nb < 4; nb++)
#pragma unroll
                    for (int q = 0; q < 4; q++) acc[mi][nb][q] = 0.f;

            for (int k16 = 0; k16 < 16; k16++) {
                const int kk = kw * 256 + k16 * 16;
                uint32_t ah[2][4], al[2][4];
#pragma unroll
                for (int mi = 0; mi < 2; mi++) {
                    int r0 = m0 + wm * 32 + mi * 16 + g;
                    int base = r0 * HDIM + kk + tg * 2;
                    uint2 u00 = __ldcg(hp + (base >> 1));
                    uint2 u10 = __ldcg(hp + ((base + 8 * HDIM) >> 1));
                    uint2 u01 = __ldcg(hp + ((base + 8) >> 1));
                    uint2 u11 = __ldcg(hp + ((base + 8 * HDIM + 8) >> 1));
                    ah[mi][0] = prmt(u00.x, u00.y, 0x5410); al[mi][0] = prmt(u00.x, u00.y, 0x7632);
                    ah[mi][1] = prmt(u10.x, u10.y, 0x5410); al[mi][1] = prmt(u10.x, u10.y, 0x7632);
                    ah[mi][2] = prmt(u01.x, u01.y, 0x5410); al[mi][2] = prmt(u01.x, u01.y, 0x7632);
                    ah[mi][3] = prmt(u11.x, u11.y, 0x5410); al[mi][3] = prmt(u11.x, u11.y, 0x7632);
                }
#pragma unroll
                for (int nb = 0; nb < 4; nb++) {
                    const char* wb = sc + O_W2 + (size_t)(nb * 8 + g) * RSB + ((kk >> 1) + tg) * 8;
                    uint2 v0 = *(const uint2*)wb;          // k, k+1  (hi | lo)
                    uint2 v1 = *(const uint2*)(wb + 32);   // k+8, k+9
#pragma unroll
                    for (int mi = 0; mi < 2; mi++) {
                        mma_bf16(acc[mi][nb], ah[mi][0], ah[mi][1], ah[mi][2], ah[mi][3], v0.x, v1.x);
                        mma_bf16(acc[mi][nb], ah[mi][0], ah[mi][1], ah[mi][2], ah[mi][3], v0.y, v1.y);
                        mma_bf16(acc[mi][nb], al[mi][0], al[mi][1], al[mi][2], al[mi][3], v0.x, v1.x);
                    }
                }
            }

            // ---- store k-split partials ----
#pragma unroll
            for (int mi = 0; mi < 2; mi++) {
                int mrow = wm * 32 + mi * 16 + g;
#pragma unroll
                for (int nb = 0; nb < 4; nb++) {
                    int col = nb * 8 + tg * 2;
                    *(float2*)&Psm[(kw * 64 + mrow) * 36 + col]     =
                        make_float2(acc[mi][nb][0], acc[mi][nb][1]);
                    *(float2*)&Psm[(kw * 64 + mrow + 8) * 36 + col] =
                        make_float2(acc[mi][nb][2], acc[mi][nb][3]);
                }
            }
            __syncthreads();

            // ---- epilogue: reduce 4 partials, bias + x*Wih, tanh, pack, store ----
            {
                int m = tid >> 2, nb8 = (tid & 3) * 8;
                float s[8];
#pragma unroll
                for (int j = 0; j < 8; j++) s[j] = 0.f;
#pragma unroll
                for (int kwi = 0; kwi < 4; kwi++) {
                    const float* pp = &Psm[(kwi * 64 + m) * 36 + nb8];
                    float4 q0 = *(const float4*)pp;
                    float4 q1 = *(const float4*)(pp + 4);
                    s[0] += q0.x; s[1] += q0.y; s[2] += q0.z; s[3] += q0.w;
                    s[4] += q1.x; s[5] += q1.y; s[6] += q1.z; s[7] += q1.w;
                }
                float xv = xs[m];
                float hv[8];
                uint32_t pk[8];
#pragma unroll
                for (int j = 0; j < 8; j++) {
                    hv[j] = tanhf(s[j] + bias_sh[nb8 + j] + xv * wih_sh[nb8 + j]);
                    pk[j] = packsplit(hv[j]);
                }
                uint32_t* dst = g_hpk[rp ^ 1] + (size_t)(m0 + m) * HDIM + n0 + nb8;
                *(uint4*)dst       = make_uint4(pk[0], pk[1], pk[2], pk[3]);
                *(uint4*)(dst + 4) = make_uint4(pk[4], pk[5], pk[6], pk[7]);
                if (phase == 1) {
                    float po = 0.f;
#pragma unroll
                    for (int j = 0; j < 8; j++) po = fmaf(hv[j], wout_sh[nb8 + j], po);
                    po += __shfl_xor_sync(0xffffffffu, po, 1);
                    po += __shfl_xor_sync(0xffffffffu, po, 2);
                    if ((tid & 3) == 0) g_xpart[t & 1][nt][m0 + m] = po;
                }
            }
            gsync(epoch);
        } // t  (final h in buf 0)

        if (phase == 0) {
            // ---- features = sigmoid(hT @ Wenc^T + benc) ----
            int d = bx * 8 + wid;
            if (d < 768) {
                int b = d / 3, e = d - 3 * b;
                const uint32_t* hpk = g_hpk[0] + (size_t)b * HDIM;
                const float* wp = Wenc + (size_t)e * HDIM;
                float s = 0.f;
                for (int k = lane * 4; k < HDIM; k += 128) {
                    uint4 w4 = __ldcg((const uint4*)(hpk + k));
                    s = fmaf(unpacksum(w4.x), wp[k],     s);
                    s = fmaf(unpacksum(w4.y), wp[k + 1], s);
                    s = fmaf(unpacksum(w4.z), wp[k + 2], s);
                    s = fmaf(unpacksum(w4.w), wp[k + 3], s);
                }
#pragma unroll
                for (int o = 16; o; o >>= 1) s += __shfl_xor_sync(0xffffffffu, s, o);
                if (lane == 0) g_feat[b * 3 + e] = 1.f / (1.f + expf(-(s + benc[e])));
            }
            gsync(epoch);
            // ---- h0 = features @ Wdec^T + bdec -> buf 0 packed ----
#pragma unroll
            for (int r = 0; r < 8; r++) {
                int i = bx * 2048 + r * 256 + tid;
                int b = i >> 10, j = i & 1023;
                float v = bdec[j] + __ldcg(&g_feat[b * 3])     * Wdec[j * 3]
                                  + __ldcg(&g_feat[b * 3 + 1]) * Wdec[j * 3 + 1]
                                  + __ldcg(&g_feat[b * 3 + 2]) * Wdec[j * 3 + 2];
                g_hpk[0][i] = packsplit(v);
            }
            gsync(epoch);
        }
    } // phases

    // ---- tail: out[:, 511] = bout + sum xpart[1] ----
    if (bx == 0) {
        float s = bout0;
#pragma unroll
        for (int j = 0; j < 32; j++) s += __ldcg(&g_xpart[1][j][tid]);
        g_out[(size_t)tid * TLEN + (TLEN - 1)] = s;
    }
    gsync(epoch);

    // ---- masked MSE numerator: 2 rows per CTA ----
    {
        int b = bx * 2 + (tid >> 7), l = tid & 127;
        int L = seqlen[b];
        float s = 0.f;
        for (int tt = l; tt < L; tt += 128) {
            float d = input[(size_t)b * TLEN + tt] - __ldcg(&g_out[(size_t)b * TLEN + tt]);
            s = fmaf(d, d, s);
        }
#pragma unroll
        for (int o = 16; o; o >>= 1) s += __shfl_xor_sync(0xffffffffu, s, o);
        if ((tid & 31) == 0) red_f[tid >> 5] = s;
        __syncthreads();
        if (tid == 0) {
            float tot = 0.f;
#pragma unroll
            for (int q = 0; q < 8; q++) tot += red_f[q];
            atomicAdd(&g_lossnum, tot);
        }
        __syncthreads();
    }
    gsync(epoch);

    // ---- finalize loss (CTA 0) ----
    if (bx == 0) {
        red_f[tid] = (float)seqlen[tid];   // BATCH == 256
        __syncthreads();
        for (int o = 128; o; o >>= 1) {
            if (tid < o) red_f[tid] += red_f[tid + o];
            __syncthreads();
        }
        if (tid == 0 && out_size > 0) dout[0] = g_lossnum / red_f[0];
    }

    // ---- pack (loss | input | output | features) ----
    {
        int chunk = (out_size + NCTA - 1) / NCTA;
        int lo = bx * chunk;
        int hi = lo + chunk; if (hi > out_size) hi = out_size;
        for (int i = lo + tid; i < hi; i += 256) {
            if (i == 0) continue;
            int j = i - 1;
            if (j < BATCH * TLEN) { dout[i] = input[j]; continue; }
            j -= BATCH * TLEN;
            if (j < BATCH * TLEN) { dout[i] = __ldcg(&g_out[j]); continue; }
            j -= BATCH * TLEN;
            if (j < BATCH * 3) { dout[i] = __ldcg(&g_feat[j]); continue; }
            dout[i] = 0.f;
        }
    }
}

extern "C" void kernel_launch(void* const* d_in, const int* in_sizes, int n_in,
                              void* d_out, int out_size) {
    const float* input  = (const float*)d_in[0];
    const int*   seqlen = (const int*)d_in[1];
    const float* Wih_e = (const float*)d_in[2];
    const float* Whh_e = (const float*)d_in[3];
    const float* bih_e = (const float*)d_in[4];
    const float* bhh_e = (const float*)d_in[5];
    const float* Wenc  = (const float*)d_in[6];
    const float* benc  = (const float*)d_in[7];
    const float* Wdec  = (const float*)d_in[8];
    const float* bdec  = (const float*)d_in[9];
    const float* Wih_d = (const float*)d_in[10];
    const float* Whh_d = (const float*)d_in[11];
    const float* bih_d = (const float*)d_in[12];
    const float* bhh_d = (const float*)d_in[13];
    const float* Wout  = (const float*)d_in[14];
    const float* bout  = (const float*)d_in[15];

    cudaFuncSetAttribute(persist_mma,
                         cudaFuncAttributeMaxDynamicSharedMemorySize, SMEM_BYTES);
    persist_mma<<<NCTA, 256, SMEM_BYTES>>>(
        input, seqlen, Wih_e, Whh_e, bih_e, bhh_e, Wenc, benc,
        Wdec, bdec, Wih_d, Whh_d, bih_d, bhh_d, Wout, bout,
        (float*)d_out, out_size);
}

// round 7
// speedup vs baseline: 4.0354x; 1.1135x over previous
#include <cuda_runtime.h>
#include <cuda_bf16.h>
#include <cstdint>

#define HDIM  1024
#define BATCH 256
#define TLEN  512
#define NCTA  128
#define NTHR  512

// ---- dynamic smem layout (bytes) ----
#define RSB    4128            // W row stride: 4096 + 32 pad
#define O_W2   0               // 132096
#define O_P    132096          // float[4][64][36] = 36864
#define O_XS   168960          // float[64]
#define O_BIAS 169216          // float[32]
#define O_WIH  169344          // float[32]
#define O_WOUT 169472          // float[32]
#define O_RED  169600          // float[256]
#define SMEM_BYTES 170624

// -------- device scratch --------
__device__ __align__(16) uint32_t g_hpk[2][BATCH * HDIM];  // lo16=hi-bf16, hi16=lo-bf16
__device__ float g_xpart[2][32][BATCH];
__device__ float g_out[BATCH * TLEN];
__device__ float g_feat[BATCH * 3];
__device__ float g_lossnum;
__device__ unsigned g_cntF;
__device__ volatile unsigned g_relF;
__device__ unsigned g_cntG[4 * 32];            // 128B-padded per group
__device__ volatile unsigned g_relG[4 * 32];

// -------- helpers --------
__device__ __forceinline__ uint32_t prmt(uint32_t a, uint32_t b, uint32_t s) {
    uint32_t d;
    asm("prmt.b32 %0, %1, %2, %3;" : "=r"(d) : "r"(a), "r"(b), "r"(s));
    return d;
}
__device__ __forceinline__ void mma_bf16(float c[4], uint32_t a0, uint32_t a1,
                                         uint32_t a2, uint32_t a3,
                                         uint32_t b0, uint32_t b1) {
    asm volatile(
        "mma.sync.aligned.m16n8k16.row.col.f32.bf16.bf16.f32 "
        "{%0,%1,%2,%3}, {%4,%5,%6,%7}, {%8,%9}, {%0,%1,%2,%3};"
        : "+f"(c[0]), "+f"(c[1]), "+f"(c[2]), "+f"(c[3])
        : "r"(a0), "r"(a1), "r"(a2), "r"(a3), "r"(b0), "r"(b1));
}
__device__ __forceinline__ uint32_t packsplit(float v) {
    __nv_bfloat16 hi = __float2bfloat16(v);
    __nv_bfloat16 lo = __float2bfloat16(v - __bfloat162float(hi));
    return (uint32_t)__bfloat16_as_ushort(hi) | ((uint32_t)__bfloat16_as_ushort(lo) << 16);
}
__device__ __forceinline__ float unpacksum(uint32_t w) {
    return __bfloat162float(__ushort_as_bfloat16((unsigned short)(w & 0xffffu))) +
           __bfloat162float(__ushort_as_bfloat16((unsigned short)(w >> 16)));
}

// -------- barriers (monotonic epochs, replay-safe) --------
__device__ __forceinline__ void gbar(unsigned* cnt, volatile unsigned* rel,
                                     unsigned n, unsigned& ep) {
    __syncthreads();
    if (threadIdx.x == 0) {
        ep++;
        __threadfence();
        unsigned old = atomicAdd(cnt, 1u);
        if (old == ep * n - 1u) {
            __threadfence();
            *rel = ep;
        } else {
            while (*rel < ep) { __nanosleep(32); }
            __threadfence();
        }
    }
    __syncthreads();
}

extern "C" __global__ void __launch_bounds__(NTHR, 1) persist_mma(
    const float* __restrict__ input, const int* __restrict__ seqlen,
    const float* __restrict__ Wih_e, const float* __restrict__ Whh_e,
    const float* __restrict__ bih_e, const float* __restrict__ bhh_e,
    const float* __restrict__ Wenc,  const float* __restrict__ benc,
    const float* __restrict__ Wdec,  const float* __restrict__ bdec,
    const float* __restrict__ Wih_d, const float* __restrict__ Whh_d,
    const float* __restrict__ bih_d, const float* __restrict__ bhh_d,
    const float* __restrict__ Wout,  const float* __restrict__ bout,
    float* __restrict__ dout, int out_size)
{
    extern __shared__ __align__(16) char sc[];
    float* Psm     = (float*)(sc + O_P);
    float* xs      = (float*)(sc + O_XS);
    float* bias_sh = (float*)(sc + O_BIAS);
    float* wih_sh  = (float*)(sc + O_WIH);
    float* wout_sh = (float*)(sc + O_WOUT);
    float* red_f   = (float*)(sc + O_RED);

    const int tid  = threadIdx.x;
    const int wid  = tid >> 5;
    const int lane = tid & 31;
    const int g    = lane >> 2;
    const int tg   = lane & 3;
    const int kw   = wid & 3;       // K-split 0..3 (256 each)
    const int wq   = wid >> 2;      // m-quarter 0..3 (16 rows each)
    const int bx   = blockIdx.x;
    const int nt   = bx & 31;
    const int mt   = bx >> 5;
    const int n0   = nt * 32;
    const int m0   = mt * 64;
    const float bout0 = bout[0];

    unsigned epF = g_relF;
    unsigned epG = g_relG[mt * 32];
    unsigned* cG = &g_cntG[mt * 32];
    volatile unsigned* rG = &g_relG[mt * 32];

    // ---- init: zero h buf 0, loss ----
    {
        int gtid = bx * NTHR + tid;                 // 65536 threads
        *(uint4*)(g_hpk[0] + gtid * 4) = make_uint4(0, 0, 0, 0);
        if (gtid == 0) g_lossnum = 0.f;
    }
    gbar(&g_cntF, &g_relF, NCTA, epF);

    // ================= two RNN phases =================
    for (int phase = 0; phase < 2; phase++) {
        const float* Whh = phase ? Whh_d : Whh_e;
        const float* Wih = phase ? Wih_d : Wih_e;
        const float* bih = phase ? bih_d : bih_e;
        const float* bhh = phase ? bhh_d : bhh_e;

        // ---- preload W slice: 32 rows x 1024, bf16 hi/lo interleaved per k-pair ----
        for (int i = tid; i < 32 * HDIM; i += NTHR) {
            int nn = i >> 10, k = i & 1023;
            float w = Whh[(size_t)(n0 + nn) * HDIM + k];
            __nv_bfloat16 hi = __float2bfloat16(w);
            __nv_bfloat16 lo = __float2bfloat16(w - __bfloat162float(hi));
            char* base = sc + O_W2 + nn * RSB + (k >> 1) * 8 + (k & 1) * 2;
            *(__nv_bfloat16*)base       = hi;
            *(__nv_bfloat16*)(base + 4) = lo;
        }
        if (tid < 32) {
            bias_sh[tid] = bih[n0 + tid] + bhh[n0 + tid];
            wih_sh[tid]  = Wih[n0 + tid];
            wout_sh[tid] = Wout[n0 + tid];
        }
        __syncthreads();

        for (int t = 0; t < TLEN; t++) {
            const int rp = t & 1;
            const uint2* hp = (const uint2*)g_hpk[rp];

            // ---- MMA mainloop: warp tile m16 x n32 over K=256, A double-buffered ----
            float acc[4][4];
#pragma unroll
            for (int nb = 0; nb < 4; nb++)
#pragma unroll
                for (int q = 0; q < 4; q++) acc[nb][q] = 0.f;

            const int r0 = m0 + wq * 16 + g;
            const size_t rowbase = (size_t)r0 * HDIM;
            uint2 cu[4], nu[4];
            {
                int base = rowbase + kw * 256 + tg * 2;
                cu[0] = __ldcg(hp + (base >> 1));
                cu[1] = __ldcg(hp + ((base + 8 * HDIM) >> 1));
                cu[2] = __ldcg(hp + ((base + 8) >> 1));
                cu[3] = __ldcg(hp + ((base + 8 * HDIM + 8) >> 1));
            }
#pragma unroll 4
            for (int k16 = 0; k16 < 16; k16++) {
                const int kk = kw * 256 + k16 * 16;
                if (k16 < 15) {
                    int base = rowbase + kk + 16 + tg * 2;
                    nu[0] = __ldcg(hp + (base >> 1));
                    nu[1] = __ldcg(hp + ((base + 8 * HDIM) >> 1));
                    nu[2] = __ldcg(hp + ((base + 8) >> 1));
                    nu[3] = __ldcg(hp + ((base + 8 * HDIM + 8) >> 1));
                }
                uint32_t ah[4], al[4];
#pragma unroll
                for (int j = 0; j < 4; j++) {
                    ah[j] = prmt(cu[j].x, cu[j].y, 0x5410);
                    al[j] = prmt(cu[j].x, cu[j].y, 0x7632);
                }
#pragma unroll
                for (int nb = 0; nb < 4; nb++) {
                    const char* wb = sc + O_W2 + (size_t)(nb * 8 + g) * RSB + ((kk >> 1) + tg) * 8;
                    uint2 v0 = *(const uint2*)wb;
                    uint2 v1 = *(const uint2*)(wb + 32);
                    mma_bf16(acc[nb], ah[0], ah[1], ah[2], ah[3], v0.x, v1.x);
                    mma_bf16(acc[nb], ah[0], ah[1], ah[2], ah[3], v0.y, v1.y);
                    mma_bf16(acc[nb], al[0], al[1], al[2], al[3], v0.x, v1.x);
                }
#pragma unroll
                for (int j = 0; j < 4; j++) cu[j] = nu[j];
            }

            // ---- store k-split partials ----
            {
                int mrow = wq * 16 + g;
#pragma unroll
                for (int nb = 0; nb < 4; nb++) {
                    int col = nb * 8 + tg * 2;
                    *(float2*)&Psm[(kw * 64 + mrow) * 36 + col]     = make_float2(acc[nb][0], acc[nb][1]);
                    *(float2*)&Psm[(kw * 64 + mrow + 8) * 36 + col] = make_float2(acc[nb][2], acc[nb][3]);
                }
            }

            // ---- per-row scalar x (overlaps with other warps' tail work) ----
            if (tid < 64) {
                float xv = 0.f;
                int row = m0 + tid;
                if (phase == 0) {
                    xv = input[(size_t)row * TLEN + t];
                } else if (t > 0) {
                    float s = 0.f;
                    const float* xp = &g_xpart[(t - 1) & 1][0][row];
#pragma unroll
                    for (int j = 0; j < 32; j++) s += __ldcg(xp + j * BATCH);
                    xv = s + bout0;
                    if (nt == 0) g_out[(size_t)row * TLEN + (t - 1)] = xv;
                }
                xs[tid] = xv;
            }
            __syncthreads();

            // ---- epilogue: reduce partials, bias + x*Wih, tanh, pack, store ----
            {
                int m = tid >> 3, c4 = (tid & 7) * 4;
                float s0 = 0.f, s1 = 0.f, s2 = 0.f, s3 = 0.f;
#pragma unroll
                for (int kwi = 0; kwi < 4; kwi++) {
                    float4 q = *(const float4*)&Psm[(kwi * 64 + m) * 36 + c4];
                    s0 += q.x; s1 += q.y; s2 += q.z; s3 += q.w;
                }
                float xv = xs[m];
                float hv[4];
                hv[0] = tanhf(s0 + bias_sh[c4]     + xv * wih_sh[c4]);
                hv[1] = tanhf(s1 + bias_sh[c4 + 1] + xv * wih_sh[c4 + 1]);
                hv[2] = tanhf(s2 + bias_sh[c4 + 2] + xv * wih_sh[c4 + 2]);
                hv[3] = tanhf(s3 + bias_sh[c4 + 3] + xv * wih_sh[c4 + 3]);
                *(uint4*)(g_hpk[rp ^ 1] + (size_t)(m0 + m) * HDIM + n0 + c4) =
                    make_uint4(packsplit(hv[0]), packsplit(hv[1]),
                               packsplit(hv[2]), packsplit(hv[3]));
                if (phase == 1) {
                    float po = hv[0] * wout_sh[c4]     + hv[1] * wout_sh[c4 + 1]
                             + hv[2] * wout_sh[c4 + 2] + hv[3] * wout_sh[c4 + 3];
                    po += __shfl_xor_sync(0xffffffffu, po, 1);
                    po += __shfl_xor_sync(0xffffffffu, po, 2);
                    po += __shfl_xor_sync(0xffffffffu, po, 4);
                    if ((tid & 7) == 0) g_xpart[t & 1][nt][m0 + m] = po;
                }
            }
            gbar(cG, rG, 32, epG);    // group-local: deps confined to this m-tile
        } // t  (final h in buf 0)

        gbar(&g_cntF, &g_relF, NCTA, epF);   // cross-group before global reads

        if (phase == 0) {
            // ---- features = sigmoid(hT @ Wenc^T + benc) ----
            int d = bx * 16 + wid;
            if (d < 768) {
                int b = d / 3, e = d - 3 * b;
                const uint32_t* hpk = g_hpk[0] + (size_t)b * HDIM;
                const float* wp = Wenc + (size_t)e * HDIM;
                float s = 0.f;
                for (int k = lane * 4; k < HDIM; k += 128) {
                    uint4 w4 = __ldcg((const uint4*)(hpk + k));
                    s = fmaf(unpacksum(w4.x), wp[k],     s);
                    s = fmaf(unpacksum(w4.y), wp[k + 1], s);
                    s = fmaf(unpacksum(w4.z), wp[k + 2], s);
                    s = fmaf(unpacksum(w4.w), wp[k + 3], s);
                }
#pragma unroll
                for (int o = 16; o; o >>= 1) s += __shfl_xor_sync(0xffffffffu, s, o);
                if (lane == 0) g_feat[b * 3 + e] = 1.f / (1.f + expf(-(s + benc[e])));
            }
            gbar(&g_cntF, &g_relF, NCTA, epF);
            // ---- h0 = features @ Wdec^T + bdec -> buf 0 packed ----
#pragma unroll
            for (int r = 0; r < 4; r++) {
                int i = bx * 2048 + r * NTHR + tid;
                int b = i >> 10, j = i & 1023;
                float v = bdec[j] + __ldcg(&g_feat[b * 3])     * Wdec[j * 3]
                                  + __ldcg(&g_feat[b * 3 + 1]) * Wdec[j * 3 + 1]
                                  + __ldcg(&g_feat[b * 3 + 2]) * Wdec[j * 3 + 2];
                g_hpk[0][i] = packsplit(v);
            }
            gbar(&g_cntF, &g_relF, NCTA, epF);
        }
    } // phases

    // ---- tail: out[:, 511] = bout + sum xpart[1] ----
    if (bx == 0 && tid < 256) {
        float s = bout0;
#pragma unroll
        for (int j = 0; j < 32; j++) s += __ldcg(&g_xpart[1][j][tid]);
        g_out[(size_t)tid * TLEN + (TLEN - 1)] = s;
    }
    gbar(&g_cntF, &g_relF, NCTA, epF);

    // ---- masked MSE numerator: 2 rows per CTA ----
    {
        int b = bx * 2 + (tid >> 8), l = tid & 255;
        int L = seqlen[b];
        float s = 0.f;
        for (int tt = l; tt < L; tt += 256) {
            float d = input[(size_t)b * TLEN + tt] - __ldcg(&g_out[(size_t)b * TLEN + tt]);
            s = fmaf(d, d, s);
        }
#pragma unroll
        for (int o = 16; o; o >>= 1) s += __shfl_xor_sync(0xffffffffu, s, o);
        if ((tid & 31) == 0) red_f[wid] = s;
        __syncthreads();
        if (tid == 0) {
            float tot = 0.f;
#pragma unroll
            for (int q = 0; q < 16; q++) tot += red_f[q];
            atomicAdd(&g_lossnum, tot);
        }
        __syncthreads();
    }
    gbar(&g_cntF, &g_relF, NCTA, epF);

    // ---- finalize loss (CTA 0) ----
    if (bx == 0) {
        if (tid < 256) red_f[tid] = (float)seqlen[tid];
        __syncthreads();
        for (int o = 128; o; o >>= 1) {
            if (tid < o) red_f[tid] += red_f[tid + o];
            __syncthreads();
        }
        if (tid == 0 && out_size > 0) dout[0] = g_lossnum / red_f[0];
    }

    // ---- pack (loss | input | output | features) ----
    {
        int chunk = (out_size + NCTA - 1) / NCTA;
        int lo = bx * chunk;
        int hi = lo + chunk; if (hi > out_size) hi = out_size;
        for (int i = lo + tid; i < hi; i += NTHR) {
            if (i == 0) continue;
            int j = i - 1;
            if (j < BATCH * TLEN) { dout[i] = input[j]; continue; }
            j -= BATCH * TLEN;
            if (j < BATCH * TLEN) { dout[i] = __ldcg(&g_out[j]); continue; }
            j -= BATCH * TLEN;
            if (j < BATCH * 3) { dout[i] = __ldcg(&g_feat[j]); continue; }
            dout[i] = 0.f;
        }
    }
}

extern "C" void kernel_launch(void* const* d_in, const int* in_sizes, int n_in,
                              void* d_out, int out_size) {
    const float* input  = (const float*)d_in[0];
    const int*   seqlen = (const int*)d_in[1];
    const float* Wih_e = (const float*)d_in[2];
    const float* Whh_e = (const float*)d_in[3];
    const float* bih_e = (const float*)d_in[4];
    const float* bhh_e = (const float*)d_in[5];
    const float* Wenc  = (const float*)d_in[6];
    const float* benc  = (const float*)d_in[7];
    const float* Wdec  = (const float*)d_in[8];
    const float* bdec  = (const float*)d_in[9];
    const float* Wih_d = (const float*)d_in[10];
    const float* Whh_d = (const float*)d_in[11];
    const float* bih_d = (const float*)d_in[12];
    const float* bhh_d = (const float*)d_in[13];
    const float* Wout  = (const float*)d_in[14];
    const float* bout  = (const float*)d_in[15];

    cudaFuncSetAttribute(persist_mma,
                         cudaFuncAttributeMaxDynamicSharedMemorySize, SMEM_BYTES);
    persist_mma<<<NCTA, NTHR, SMEM_BYTES>>>(
        input, seqlen, Wih_e, Whh_e, bih_e, bhh_e, Wenc, benc,
        Wdec, bdec, Wih_d, Whh_d, bih_d, bhh_d, Wout, bout,
        (float*)d_out, out_size);
}